// round 1
// baseline (speedup 1.0000x reference)
#include <cuda_runtime.h>
#include <cuda_bf16.h>

// Problem constants
#define Bn   8
#define CHn  7
#define Hn   256
#define Wn   256
#define NBR  6
#define C1   64
#define PX   4          // pixels per thread along W
#define WSTR 24         // padded per-(n,c) weight stride in smem (18 -> 24 floats, 96B 16-aligned)

// Scratch for the "combined" (B,7,H,W) tensor between the two kernels.
__device__ float g_comb[Bn * CHn * Hn * Wn];

// ---------------------------------------------------------------------------
// Kernel 1: the 6 similarity branches, fully fused.
// For each pixel and neighbor n:
//   h_c   = relu( b1[n,c] + sum_{ic,kh,kw} W1[n,c,ic,kh,kw] * pair[ic] )   (c = 0..63)
//   logit = b2[n] + sum_c W2[n,c] * h_c
//   sim   = sigmoid(logit)
//   comb[n-channel] = sim * check_center
// comb[3] = base (pass-through).
// pair channel order: n<3 -> (base, check); n>=3 -> (check, base). We pre-swap
// the two 9-tap halves of W1 in shared memory so base weights always sit at
// offset 0 and check weights at offset 12 (compile-time offsets, full unroll).
// ---------------------------------------------------------------------------
__global__ __launch_bounds__(256, 4) void branch_kernel(
    const float* __restrict__ x,
    const float* __restrict__ W1, const float* __restrict__ b1,
    const float* __restrict__ W2, const float* __restrict__ b2)
{
    __shared__ float W1s[NBR * C1 * WSTR];   // [n][c][24]: base taps @0..8, check taps @12..20
    __shared__ float b1s[NBR * C1];
    __shared__ float W2s[NBR * C1];
    __shared__ float b2s[NBR];

    const int tid = threadIdx.y * 64 + threadIdx.x;

    // Stage weights: W1 layout (NBR, 64, 2, 3, 3)
    for (int i = tid; i < NBR * C1 * 18; i += 256) {
        int nc = i / 18, k = i % 18;
        int n  = nc / C1;
        int ic = k / 9, r = k % 9;
        // logical input channel 0 is BASE for n<3, CHECK for n>=3
        int base_ic = (n < 3) ? 0 : 1;
        int slot    = (ic == base_ic) ? r : (12 + r);
        W1s[nc * WSTR + slot] = W1[i];
    }
    for (int i = tid; i < NBR * C1; i += 256) { b1s[i] = b1[i]; W2s[i] = W2[i]; }
    if (tid < NBR) b2s[tid] = b2[tid];
    __syncthreads();

    const int b  = blockIdx.y;
    const int h  = blockIdx.x * 4 + threadIdx.y;
    const int w0 = threadIdx.x * PX;

    // Load the base 3x(PX+2) window (zero padding at borders).
    const float* xb = x + ((size_t)(b * CHn + 3)) * Hn * Wn;
    float basewin[3][PX + 2];
    #pragma unroll
    for (int r = 0; r < 3; r++) {
        int hh = h - 1 + r;
        bool hok = (hh >= 0) && (hh < Hn);
        #pragma unroll
        for (int c = 0; c < PX + 2; c++) {
            int ww = w0 - 1 + c;
            basewin[r][c] = (hok && ww >= 0 && ww < Wn) ? __ldg(&xb[hh * Wn + ww]) : 0.f;
        }
    }

    // comb channel 3 = base
    {
        float* combbase = g_comb + (((size_t)(b * CHn + 3)) * Hn + h) * Wn + w0;
        #pragma unroll
        for (int p = 0; p < PX; p++) combbase[p] = basewin[1][p + 1];
    }

    #pragma unroll 1
    for (int n = 0; n < NBR; n++) {
        const int srcch = (n < 3) ? n : n + 1;
        const float* xc = x + ((size_t)(b * CHn + srcch)) * Hn * Wn;
        float chkwin[3][PX + 2];
        #pragma unroll
        for (int r = 0; r < 3; r++) {
            int hh = h - 1 + r;
            bool hok = (hh >= 0) && (hh < Hn);
            #pragma unroll
            for (int c = 0; c < PX + 2; c++) {
                int ww = w0 - 1 + c;
                chkwin[r][c] = (hok && ww >= 0 && ww < Wn) ? __ldg(&xc[hh * Wn + ww]) : 0.f;
            }
        }

        float sim[PX];
        const float bb2 = b2s[n];
        #pragma unroll
        for (int p = 0; p < PX; p++) sim[p] = bb2;

        const float* wbase = &W1s[n * C1 * WSTR];
        const float* b1p   = &b1s[n * C1];
        const float* w2p   = &W2s[n * C1];

        #pragma unroll 4
        for (int c = 0; c < C1; c++) {
            const float* wc = wbase + c * WSTR;
            const float bbv = b1p[c];
            float acc[PX];
            #pragma unroll
            for (int p = 0; p < PX; p++) acc[p] = bbv;

            #pragma unroll
            for (int kh = 0; kh < 3; kh++) {
                #pragma unroll
                for (int kw = 0; kw < 3; kw++) {
                    const float wbv = wc[kh * 3 + kw];        // base tap
                    const float wcv = wc[12 + kh * 3 + kw];   // check tap
                    #pragma unroll
                    for (int p = 0; p < PX; p++) {
                        acc[p] = fmaf(wbv, basewin[kh][kw + p], acc[p]);
                        acc[p] = fmaf(wcv, chkwin[kh][kw + p], acc[p]);
                    }
                }
            }
            const float w2v = w2p[c];
            #pragma unroll
            for (int p = 0; p < PX; p++)
                sim[p] = fmaf(w2v, fmaxf(acc[p], 0.f), sim[p]);
        }

        float* combp = g_comb + (((size_t)(b * CHn + srcch)) * Hn + h) * Wn + w0;
        #pragma unroll
        for (int p = 0; p < PX; p++) {
            float s = 1.f / (1.f + __expf(-sim[p]));
            combp[p] = s * chkwin[1][p + 1];
        }
    }
}

// ---------------------------------------------------------------------------
// Kernel 2: final 7->7 3x3 SAME conv over the combined tensor.
// ---------------------------------------------------------------------------
__global__ __launch_bounds__(256, 4) void mix_kernel(
    const float* __restrict__ Wm, const float* __restrict__ bm,
    float* __restrict__ out)
{
    __shared__ float Wms[7 * 7 * 9];
    __shared__ float bms[7];

    const int tid = threadIdx.y * 64 + threadIdx.x;
    for (int i = tid; i < 7 * 7 * 9; i += 256) Wms[i] = Wm[i];
    if (tid < 7) bms[tid] = bm[tid];
    __syncthreads();

    const int b  = blockIdx.y;
    const int h  = blockIdx.x * 4 + threadIdx.y;
    const int w0 = threadIdx.x * PX;

    float acc[7][PX];
    #pragma unroll
    for (int o = 0; o < 7; o++) {
        const float bv = bms[o];
        #pragma unroll
        for (int p = 0; p < PX; p++) acc[o][p] = bv;
    }

    #pragma unroll 1
    for (int ic = 0; ic < 7; ic++) {
        const float* xp = g_comb + ((size_t)(b * CHn + ic)) * Hn * Wn;
        float win[3][PX + 2];
        #pragma unroll
        for (int r = 0; r < 3; r++) {
            int hh = h - 1 + r;
            bool hok = (hh >= 0) && (hh < Hn);
            #pragma unroll
            for (int c = 0; c < PX + 2; c++) {
                int ww = w0 - 1 + c;
                win[r][c] = (hok && ww >= 0 && ww < Wn) ? xp[hh * Wn + ww] : 0.f;
            }
        }
        #pragma unroll
        for (int o = 0; o < 7; o++) {
            #pragma unroll
            for (int kh = 0; kh < 3; kh++) {
                #pragma unroll
                for (int kw = 0; kw < 3; kw++) {
                    const float wv = Wms[(o * 7 + ic) * 9 + kh * 3 + kw];
                    #pragma unroll
                    for (int p = 0; p < PX; p++)
                        acc[o][p] = fmaf(wv, win[kh][kw + p], acc[o][p]);
                }
            }
        }
    }

    #pragma unroll
    for (int o = 0; o < 7; o++) {
        float* op = out + (((size_t)(b * CHn + o)) * Hn + h) * Wn + w0;
        #pragma unroll
        for (int p = 0; p < PX; p++) op[p] = acc[o][p];
    }
}

// ---------------------------------------------------------------------------
// kernel_launch: graph-capturable, allocation-free.
// Input order (metadata): x, W1, b1, W2, b2, Wm, bm
// ---------------------------------------------------------------------------
extern "C" void kernel_launch(void* const* d_in, const int* in_sizes, int n_in,
                              void* d_out, int out_size)
{
    const float* x  = (const float*)d_in[0];
    const float* W1 = (const float*)d_in[1];
    const float* b1 = (const float*)d_in[2];
    const float* W2 = (const float*)d_in[3];
    const float* b2 = (const float*)d_in[4];
    const float* Wm = (const float*)d_in[5];
    const float* bm = (const float*)d_in[6];
    float* out = (float*)d_out;

    dim3 block(64, 4, 1);        // 64 threads * 4 px = 256 cols; 4 rows
    dim3 grid(Hn / 4, Bn, 1);    // 64 row-tiles, 8 batches

    branch_kernel<<<grid, block>>>(x, W1, b1, W2, b2);
    mix_kernel<<<grid, block>>>(Wm, bm, out);
}